// round 12
// baseline (speedup 1.0000x reference)
#include <cuda_runtime.h>
#include <cstddef>

#define NUSERS 200000
#define NITEMS 100000
#define DIM    64
#define NEDGES 3200000

// -------- scratch (no allocations allowed; __device__ globals are the sanctioned path) ----
__device__ __align__(256) float g_hu[(size_t)NUSERS * DIM];
__device__ __align__(256) float g_hi[(size_t)NITEMS * DIM];
__device__ __align__(256) float g_nu[(size_t)NUSERS * DIM];
__device__ __align__(256) float g_ni[(size_t)NITEMS * DIM];

// CSR scratch (rebuilt every call; no caching)
__device__ int  g_cnt_u[NUSERS];
__device__ int  g_rp_u[NUSERS + 1];
__device__ int  g_pos_u[NUSERS];
__device__ int2 g_edge_u[NEDGES];      // {src_item, w_bits}
__device__ int  g_cnt_i[NITEMS];
__device__ int  g_rp_i[NITEMS + 1];
__device__ int  g_pos_i[NITEMS];
__device__ int2 g_edge_i[NEDGES];      // {src_user, w_bits}
__device__ int  g_bsum_u[256];
__device__ int  g_bsum_i[256];

// ---------------------------------------------------------------------------
// CSR build: histogram -> 3-kernel exclusive scan -> edge scatter
// ---------------------------------------------------------------------------
__global__ void hist_kernel(const int* __restrict__ idx, int* __restrict__ cnt, int n) {
    int e = blockIdx.x * blockDim.x + threadIdx.x;
    if (e < n) atomicAdd(cnt + idx[e], 1);
}

__global__ void scan_blocksum(const int* __restrict__ cnt, int* __restrict__ bsum, int n) {
    __shared__ int sh[1024];
    int i = blockIdx.x * 1024 + threadIdx.x;
    int v = (i < n) ? cnt[i] : 0;
    sh[threadIdx.x] = v;
    __syncthreads();
    for (int o = 512; o > 0; o >>= 1) {
        if (threadIdx.x < o) sh[threadIdx.x] += sh[threadIdx.x + o];
        __syncthreads();
    }
    if (threadIdx.x == 0) bsum[blockIdx.x] = sh[0];
}

__global__ void scan_bsums(int* __restrict__ bsum, int nb) {   // single block, 256 thr
    __shared__ int sh[256];
    int t = threadIdx.x;
    int v = (t < nb) ? bsum[t] : 0;
    sh[t] = v;
    __syncthreads();
    for (int o = 1; o < 256; o <<= 1) {
        int x = (t >= o) ? sh[t - o] : 0;
        __syncthreads();
        sh[t] += x;
        __syncthreads();
    }
    if (t < nb) bsum[t] = sh[t] - v;   // exclusive
}

__global__ void scan_write(const int* __restrict__ cnt, const int* __restrict__ bsum,
                           int* __restrict__ rowptr, int* __restrict__ pos, int n) {
    __shared__ int sh[1024];
    int t = threadIdx.x;
    int i = blockIdx.x * 1024 + t;
    int v = (i < n) ? cnt[i] : 0;
    sh[t] = v;
    __syncthreads();
    for (int o = 1; o < 1024; o <<= 1) {
        int x = (t >= o) ? sh[t - o] : 0;
        __syncthreads();
        sh[t] += x;
        __syncthreads();
    }
    if (i < n) {
        int start = bsum[blockIdx.x] + sh[t] - v;
        rowptr[i] = start;
        pos[i]    = start;
    }
    if (i == 0) rowptr[n] = NEDGES;
}

__global__ void scatter_edges(const int* __restrict__ dst, const int* __restrict__ src,
                              const float* __restrict__ w, int* __restrict__ pos,
                              int2* __restrict__ edges, int n) {
    int e = blockIdx.x * blockDim.x + threadIdx.x;
    if (e >= n) return;
    int p = atomicAdd(pos + dst[e], 1);
    edges[p] = make_int2(src[e], __float_as_int(w[e]));
}

// ---------------------------------------------------------------------------
// Gather SpMM: out[r] = sum_{j in row r} w_j * h[src_j]   (warp per row)
// 4-deep edge unroll: 4 independent meta loads, then 4 independent row
// gathers in flight (MLP=4), then 16 FMAs. Edge stream uses evict-first.
// ---------------------------------------------------------------------------
__device__ __forceinline__ int2 ldcs_int2(const int2* p) {
    int2 r;
    asm volatile("ld.global.cs.v2.s32 {%0,%1}, [%2];"
                 : "=r"(r.x), "=r"(r.y) : "l"(p));
    return r;
}

__global__ void __launch_bounds__(256) spmm_gather(
    const float* __restrict__ h,
    const int*   __restrict__ rowptr,
    const int2*  __restrict__ edges,
    float*       __restrict__ out,
    int nrows)
{
    int warp = (blockIdx.x * 256 + threadIdx.x) >> 5;
    int lane = threadIdx.x & 31;
    if (warp >= nrows) return;

    int start = __ldg(rowptr + warp);
    int end   = __ldg(rowptr + warp + 1);

    float2 acc = make_float2(0.f, 0.f);
    int j = start;

    for (; j + 4 <= end; j += 4) {
        int2 e0 = ldcs_int2(edges + j);
        int2 e1 = ldcs_int2(edges + j + 1);
        int2 e2 = ldcs_int2(edges + j + 2);
        int2 e3 = ldcs_int2(edges + j + 3);
        float2 v0 = *reinterpret_cast<const float2*>(h + (size_t)e0.x * DIM + 2 * lane);
        float2 v1 = *reinterpret_cast<const float2*>(h + (size_t)e1.x * DIM + 2 * lane);
        float2 v2 = *reinterpret_cast<const float2*>(h + (size_t)e2.x * DIM + 2 * lane);
        float2 v3 = *reinterpret_cast<const float2*>(h + (size_t)e3.x * DIM + 2 * lane);
        float w0 = __int_as_float(e0.y), w1 = __int_as_float(e1.y);
        float w2 = __int_as_float(e2.y), w3 = __int_as_float(e3.y);
        acc.x = fmaf(w0, v0.x, acc.x);  acc.y = fmaf(w0, v0.y, acc.y);
        acc.x = fmaf(w1, v1.x, acc.x);  acc.y = fmaf(w1, v1.y, acc.y);
        acc.x = fmaf(w2, v2.x, acc.x);  acc.y = fmaf(w2, v2.y, acc.y);
        acc.x = fmaf(w3, v3.x, acc.x);  acc.y = fmaf(w3, v3.y, acc.y);
    }
    for (; j < end; j++) {
        int2 e0 = ldcs_int2(edges + j);
        float2 v0 = *reinterpret_cast<const float2*>(h + (size_t)e0.x * DIM + 2 * lane);
        float w0 = __int_as_float(e0.y);
        acc.x = fmaf(w0, v0.x, acc.x);
        acc.y = fmaf(w0, v0.y, acc.y);
    }
    *reinterpret_cast<float2*>(out + (size_t)warp * DIM + 2 * lane) = acc;
}

// ---------------------------------------------------------------------------
// Register-tiled fused dense+relu+L2norm, K split in 2 chunks of 64.
// Mainloop steps k by 4 with float4 x loads.
// ---------------------------------------------------------------------------
#define SX_STRIDE 68
#define SW_STRIDE 68
#define DN_SMEM ((128 * SX_STRIDE + 64 * SW_STRIDE) * 4)

__global__ void __launch_bounds__(256, 4) dense_norm_tiled(
    const float* __restrict__ h,
    const float* __restrict__ neigh,
    const float* __restrict__ W,       // [64][128] row-major
    float*       __restrict__ out,
    int nrows)
{
    extern __shared__ float smem[];
    float* sX = smem;                    // [128][SX_STRIDE]
    float* sW = smem + 128 * SX_STRIDE;  // [64][SW_STRIDE]

    const int t    = threadIdx.x;
    const int tx   = t & 7;
    const int ty   = t >> 3;
    const int row0 = blockIdx.x * 128;

    float acc[4][8];
    #pragma unroll
    for (int i = 0; i < 4; i++)
        #pragma unroll
        for (int j = 0; j < 8; j++) acc[i][j] = 0.f;

    #pragma unroll
    for (int c = 0; c < 2; c++) {
        const float* xsrc = (c == 0) ? h : neigh;
        if (c) __syncthreads();

        #pragma unroll
        for (int i = 0; i < 8; i++) {
            int idx = t + i * 256;
            int m   = idx >> 4;
            int kq  = idx & 15;
            int row = row0 + m;
            float4 v = make_float4(0.f, 0.f, 0.f, 0.f);
            if (row < nrows)
                v = *reinterpret_cast<const float4*>(xsrc + (size_t)row * DIM + 4 * kq);
            *reinterpret_cast<float4*>(sX + m * SX_STRIDE + 4 * kq) = v;
        }
        #pragma unroll
        for (int i = 0; i < 4; i++) {
            int idx = t + i * 256;
            int j   = idx >> 4;
            int kq  = idx & 15;
            float4 v = *reinterpret_cast<const float4*>(W + j * 128 + c * 64 + 4 * kq);
            sW[(4 * kq + 0) * SW_STRIDE + j] = v.x;
            sW[(4 * kq + 1) * SW_STRIDE + j] = v.y;
            sW[(4 * kq + 2) * SW_STRIDE + j] = v.z;
            sW[(4 * kq + 3) * SW_STRIDE + j] = v.w;
        }
        __syncthreads();

        const float* xb = sX + (ty * 4) * SX_STRIDE;
        const float* wb = sW + tx * 8;

        #pragma unroll
        for (int k0 = 0; k0 < 64; k0 += 4) {
            float4 xq[4];
            #pragma unroll
            for (int i = 0; i < 4; i++)
                xq[i] = *reinterpret_cast<const float4*>(xb + i * SX_STRIDE + k0);

            #pragma unroll
            for (int d = 0; d < 4; d++) {
                float4 w0 = *reinterpret_cast<const float4*>(wb + (k0 + d) * SW_STRIDE);
                float4 w1 = *reinterpret_cast<const float4*>(wb + (k0 + d) * SW_STRIDE + 4);
                #pragma unroll
                for (int i = 0; i < 4; i++) {
                    float xi = (d == 0) ? xq[i].x : (d == 1) ? xq[i].y
                             : (d == 2) ? xq[i].z : xq[i].w;
                    acc[i][0] = fmaf(xi, w0.x, acc[i][0]);
                    acc[i][1] = fmaf(xi, w0.y, acc[i][1]);
                    acc[i][2] = fmaf(xi, w0.z, acc[i][2]);
                    acc[i][3] = fmaf(xi, w0.w, acc[i][3]);
                    acc[i][4] = fmaf(xi, w1.x, acc[i][4]);
                    acc[i][5] = fmaf(xi, w1.y, acc[i][5]);
                    acc[i][6] = fmaf(xi, w1.z, acc[i][6]);
                    acc[i][7] = fmaf(xi, w1.w, acc[i][7]);
                }
            }
        }
    }

    #pragma unroll
    for (int i = 0; i < 4; i++) {
        float ss = 0.f;
        #pragma unroll
        for (int j = 0; j < 8; j++) {
            float v = fmaxf(acc[i][j], 0.f);
            acc[i][j] = v;
            ss = fmaf(v, v, ss);
        }
        ss += __shfl_xor_sync(0xffffffffu, ss, 1);
        ss += __shfl_xor_sync(0xffffffffu, ss, 2);
        ss += __shfl_xor_sync(0xffffffffu, ss, 4);
        float s = 1.0f / fmaxf(sqrtf(ss), 1e-12f);

        int row = row0 + ty * 4 + i;
        if (row < nrows) {
            float* op = out + (size_t)row * DIM + tx * 8;
            *reinterpret_cast<float4*>(op) =
                make_float4(acc[i][0] * s, acc[i][1] * s, acc[i][2] * s, acc[i][3] * s);
            *reinterpret_cast<float4*>(op + 4) =
                make_float4(acc[i][4] * s, acc[i][5] * s, acc[i][6] * s, acc[i][7] * s);
        }
    }
}

// ---------------------------------------------------------------------------
static void build_csr(cudaStream_t s, const int* dst, const int* src, const float* w,
                      int* cnt, int* bsum, int* rowptr, int* pos, int2* edges, int nrows)
{
    cudaMemsetAsync(cnt, 0, nrows * sizeof(int), s);
    hist_kernel<<<(NEDGES + 255) / 256, 256, 0, s>>>(dst, cnt, NEDGES);
    int nb = (nrows + 1023) / 1024;
    scan_blocksum<<<nb, 1024, 0, s>>>(cnt, bsum, nrows);
    scan_bsums<<<1, 256, 0, s>>>(bsum, nb);
    scan_write<<<nb, 1024, 0, s>>>(cnt, bsum, rowptr, pos, nrows);
    scatter_edges<<<(NEDGES + 255) / 256, 256, 0, s>>>(dst, src, w, pos, edges, NEDGES);
}

extern "C" void kernel_launch(void* const* d_in, const int* in_sizes, int n_in,
                              void* d_out, int out_size)
{
    const float* user_emb = (const float*)d_in[0];
    const float* item_emb = (const float*)d_in[1];
    const float* Wu       = (const float*)d_in[2];   // [2][64][128]
    const float* Wi       = (const float*)d_in[3];
    const int*   u_idx    = (const int*)  d_in[4];
    const int*   i_idx    = (const int*)  d_in[5];
    const float* w_u2i    = (const float*)d_in[6];
    const float* w_i2u    = (const float*)d_in[7];

    float* out_u = (float*)d_out;
    float* out_i = out_u + (size_t)NUSERS * DIM;

    float *hu, *hi, *nu, *ni;
    int *cnt_u, *rp_u, *pos_u, *cnt_i, *rp_i, *pos_i, *bsum_u, *bsum_i;
    int2 *edge_u, *edge_i;
    cudaGetSymbolAddress((void**)&hu, g_hu);
    cudaGetSymbolAddress((void**)&hi, g_hi);
    cudaGetSymbolAddress((void**)&nu, g_nu);
    cudaGetSymbolAddress((void**)&ni, g_ni);
    cudaGetSymbolAddress((void**)&cnt_u, g_cnt_u);
    cudaGetSymbolAddress((void**)&rp_u,  g_rp_u);
    cudaGetSymbolAddress((void**)&pos_u, g_pos_u);
    cudaGetSymbolAddress((void**)&edge_u, g_edge_u);
    cudaGetSymbolAddress((void**)&cnt_i, g_cnt_i);
    cudaGetSymbolAddress((void**)&rp_i,  g_rp_i);
    cudaGetSymbolAddress((void**)&pos_i, g_pos_i);
    cudaGetSymbolAddress((void**)&edge_i, g_edge_i);
    cudaGetSymbolAddress((void**)&bsum_u, g_bsum_u);
    cudaGetSymbolAddress((void**)&bsum_i, g_bsum_i);

    static cudaStream_t s1 = nullptr;
    static cudaEvent_t evFork = nullptr, evHU = nullptr, evHI = nullptr, evEnd = nullptr;
    if (!s1) {
        cudaFuncSetAttribute(dense_norm_tiled,
                             cudaFuncAttributeMaxDynamicSharedMemorySize, DN_SMEM);
        cudaStreamCreateWithFlags(&s1, cudaStreamNonBlocking);
        cudaEventCreateWithFlags(&evFork, cudaEventDisableTiming);
        cudaEventCreateWithFlags(&evHU,   cudaEventDisableTiming);
        cudaEventCreateWithFlags(&evHI,   cudaEventDisableTiming);
        cudaEventCreateWithFlags(&evEnd,  cudaEventDisableTiming);
    }

    const int gather_u_blks = (NUSERS * 32 + 255) / 256;   // warp per row
    const int gather_i_blks = (NITEMS * 32 + 255) / 256;
    const int dense_u_blks  = (NUSERS + 127) / 128;
    const int dense_i_blks  = (NITEMS + 127) / 128;

    cudaStream_t s0 = 0;

    cudaEventRecord(evFork, s0);
    cudaStreamWaitEvent(s1, evFork, 0);

    // ---- CSR builds (independent; one per stream) ----
    build_csr(s0, u_idx, i_idx, w_u2i, cnt_u, bsum_u, rp_u, pos_u, edge_u, NUSERS);
    build_csr(s1, i_idx, u_idx, w_i2u, cnt_i, bsum_i, rp_i, pos_i, edge_i, NITEMS);

    // ---------------- Layer 0 ----------------
    spmm_gather<<<gather_u_blks, 256, 0, s0>>>(item_emb, rp_u, edge_u, nu, NUSERS);
    dense_norm_tiled<<<dense_u_blks, 256, DN_SMEM, s0>>>(user_emb, nu, Wu, hu, NUSERS);
    cudaEventRecord(evHU, s0);

    spmm_gather<<<gather_i_blks, 256, 0, s1>>>(user_emb, rp_i, edge_i, ni, NITEMS);
    dense_norm_tiled<<<dense_i_blks, 256, DN_SMEM, s1>>>(item_emb, ni, Wi, hi, NITEMS);
    cudaEventRecord(evHI, s1);

    // ---------------- Layer 1 ----------------
    cudaStreamWaitEvent(s0, evHI, 0);
    spmm_gather<<<gather_u_blks, 256, 0, s0>>>(hi, rp_u, edge_u, nu, NUSERS);
    dense_norm_tiled<<<dense_u_blks, 256, DN_SMEM, s0>>>(hu, nu, Wu + 64 * 128, out_u, NUSERS);

    cudaStreamWaitEvent(s1, evHU, 0);
    spmm_gather<<<gather_i_blks, 256, 0, s1>>>(hu, rp_i, edge_i, ni, NITEMS);
    dense_norm_tiled<<<dense_i_blks, 256, DN_SMEM, s1>>>(hi, ni, Wi + 64 * 128, out_i, NITEMS);

    cudaEventRecord(evEnd, s1);
    cudaStreamWaitEvent(s0, evEnd, 0);
}

// round 13
// speedup vs baseline: 1.1070x; 1.1070x over previous
#include <cuda_runtime.h>
#include <cstddef>

#define NUSERS 200000
#define NITEMS 100000
#define DIM    64
#define NEDGES 3200000

// -------- scratch (no allocations allowed; __device__ globals are the sanctioned path) ----
__device__ __align__(256) float g_hu[(size_t)NUSERS * DIM];
__device__ __align__(256) float g_hi[(size_t)NITEMS * DIM];
__device__ __align__(256) float g_nu[(size_t)NUSERS * DIM];
__device__ __align__(256) float g_ni[(size_t)NITEMS * DIM];

// CSR scratch (rebuilt every call; no caching)
__device__ int  g_cnt_u[NUSERS];
__device__ int  g_rp_u[NUSERS + 1];
__device__ int  g_pos_u[NUSERS];
__device__ int2 g_edge_u[NEDGES];      // {src_item, w_bits}
__device__ int  g_cnt_i[NITEMS];
__device__ int  g_rp_i[NITEMS + 1];
__device__ int  g_pos_i[NITEMS];
__device__ int2 g_edge_i[NEDGES];      // {src_user, w_bits}
__device__ int  g_bsum_u[256];
__device__ int  g_bsum_i[256];

// ---------------------------------------------------------------------------
// CSR build: histogram -> 3-kernel exclusive scan -> edge scatter
// ---------------------------------------------------------------------------
__global__ void hist_kernel(const int* __restrict__ idx, int* __restrict__ cnt, int n) {
    int e = blockIdx.x * blockDim.x + threadIdx.x;
    if (e < n) atomicAdd(cnt + idx[e], 1);
}

__global__ void scan_blocksum(const int* __restrict__ cnt, int* __restrict__ bsum, int n) {
    __shared__ int sh[1024];
    int i = blockIdx.x * 1024 + threadIdx.x;
    int v = (i < n) ? cnt[i] : 0;
    sh[threadIdx.x] = v;
    __syncthreads();
    for (int o = 512; o > 0; o >>= 1) {
        if (threadIdx.x < o) sh[threadIdx.x] += sh[threadIdx.x + o];
        __syncthreads();
    }
    if (threadIdx.x == 0) bsum[blockIdx.x] = sh[0];
}

__global__ void scan_bsums(int* __restrict__ bsum, int nb) {   // single block, 256 thr
    __shared__ int sh[256];
    int t = threadIdx.x;
    int v = (t < nb) ? bsum[t] : 0;
    sh[t] = v;
    __syncthreads();
    for (int o = 1; o < 256; o <<= 1) {
        int x = (t >= o) ? sh[t - o] : 0;
        __syncthreads();
        sh[t] += x;
        __syncthreads();
    }
    if (t < nb) bsum[t] = sh[t] - v;   // exclusive
}

__global__ void scan_write(const int* __restrict__ cnt, const int* __restrict__ bsum,
                           int* __restrict__ rowptr, int* __restrict__ pos, int n) {
    __shared__ int sh[1024];
    int t = threadIdx.x;
    int i = blockIdx.x * 1024 + t;
    int v = (i < n) ? cnt[i] : 0;
    sh[t] = v;
    __syncthreads();
    for (int o = 1; o < 1024; o <<= 1) {
        int x = (t >= o) ? sh[t - o] : 0;
        __syncthreads();
        sh[t] += x;
        __syncthreads();
    }
    if (i < n) {
        int start = bsum[blockIdx.x] + sh[t] - v;
        rowptr[i] = start;
        pos[i]    = start;
    }
    if (i == 0) rowptr[n] = NEDGES;
}

__global__ void scatter_edges(const int* __restrict__ dst, const int* __restrict__ src,
                              const float* __restrict__ w, int* __restrict__ pos,
                              int2* __restrict__ edges, int n) {
    int e = blockIdx.x * blockDim.x + threadIdx.x;
    if (e >= n) return;
    int p = atomicAdd(pos + dst[e], 1);
    edges[p] = make_int2(src[e], __float_as_int(w[e]));
}

// ---------------------------------------------------------------------------
// Gather SpMM: out[r] = sum_{j in row r} w_j * h[src_j]   (warp per row)
// 4-deep edge unroll with plain __ldg: 4 independent meta loads, then 4
// independent row gathers in flight (MLP=4), then 16 FMAs.
// ---------------------------------------------------------------------------
__global__ void __launch_bounds__(256) spmm_gather(
    const float* __restrict__ h,
    const int*   __restrict__ rowptr,
    const int2*  __restrict__ edges,
    float*       __restrict__ out,
    int nrows)
{
    int warp = (blockIdx.x * 256 + threadIdx.x) >> 5;
    int lane = threadIdx.x & 31;
    if (warp >= nrows) return;

    int start = __ldg(rowptr + warp);
    int end   = __ldg(rowptr + warp + 1);

    float2 acc = make_float2(0.f, 0.f);
    int j = start;

    for (; j + 4 <= end; j += 4) {
        int2 e0 = __ldg(edges + j);
        int2 e1 = __ldg(edges + j + 1);
        int2 e2 = __ldg(edges + j + 2);
        int2 e3 = __ldg(edges + j + 3);
        float2 v0 = *reinterpret_cast<const float2*>(h + (size_t)e0.x * DIM + 2 * lane);
        float2 v1 = *reinterpret_cast<const float2*>(h + (size_t)e1.x * DIM + 2 * lane);
        float2 v2 = *reinterpret_cast<const float2*>(h + (size_t)e2.x * DIM + 2 * lane);
        float2 v3 = *reinterpret_cast<const float2*>(h + (size_t)e3.x * DIM + 2 * lane);
        float w0 = __int_as_float(e0.y), w1 = __int_as_float(e1.y);
        float w2 = __int_as_float(e2.y), w3 = __int_as_float(e3.y);
        acc.x = fmaf(w0, v0.x, acc.x);  acc.y = fmaf(w0, v0.y, acc.y);
        acc.x = fmaf(w1, v1.x, acc.x);  acc.y = fmaf(w1, v1.y, acc.y);
        acc.x = fmaf(w2, v2.x, acc.x);  acc.y = fmaf(w2, v2.y, acc.y);
        acc.x = fmaf(w3, v3.x, acc.x);  acc.y = fmaf(w3, v3.y, acc.y);
    }
    for (; j < end; j++) {
        int2 e0 = __ldg(edges + j);
        float2 v0 = *reinterpret_cast<const float2*>(h + (size_t)e0.x * DIM + 2 * lane);
        float w0 = __int_as_float(e0.y);
        acc.x = fmaf(w0, v0.x, acc.x);
        acc.y = fmaf(w0, v0.y, acc.y);
    }
    *reinterpret_cast<float2*>(out + (size_t)warp * DIM + 2 * lane) = acc;
}

// ---------------------------------------------------------------------------
// Register-tiled fused dense+relu+L2norm, K split in 2 chunks of 64.
// EXACT 742us-best mainloop (k-by-1, scalar x LDS): stays within 64 regs
// under __launch_bounds__(256,4) -> no spills, 4 blocks/SM.
// ---------------------------------------------------------------------------
#define SX_STRIDE 68
#define SW_STRIDE 68
#define DN_SMEM ((128 * SX_STRIDE + 64 * SW_STRIDE) * 4)

__global__ void __launch_bounds__(256, 4) dense_norm_tiled(
    const float* __restrict__ h,
    const float* __restrict__ neigh,
    const float* __restrict__ W,     // [64][128] row-major
    float*       __restrict__ out,
    int nrows)
{
    extern __shared__ float smem[];
    float* sX = smem;                    // [128][SX_STRIDE]
    float* sW = smem + 128 * SX_STRIDE;  // [64][SW_STRIDE]

    const int t    = threadIdx.x;
    const int tx   = t & 7;
    const int ty   = t >> 3;
    const int row0 = blockIdx.x * 128;

    float acc[4][8];
    #pragma unroll
    for (int i = 0; i < 4; i++)
        #pragma unroll
        for (int j = 0; j < 8; j++) acc[i][j] = 0.f;

    #pragma unroll
    for (int c = 0; c < 2; c++) {
        const float* xsrc = (c == 0) ? h : neigh;
        if (c) __syncthreads();

        #pragma unroll
        for (int i = 0; i < 8; i++) {
            int idx = t + i * 256;
            int m   = idx >> 4;
            int kq  = idx & 15;
            int row = row0 + m;
            float4 v = make_float4(0.f, 0.f, 0.f, 0.f);
            if (row < nrows)
                v = *reinterpret_cast<const float4*>(xsrc + (size_t)row * DIM + 4 * kq);
            *reinterpret_cast<float4*>(sX + m * SX_STRIDE + 4 * kq) = v;
        }
        #pragma unroll
        for (int i = 0; i < 4; i++) {
            int idx = t + i * 256;
            int j   = idx >> 4;
            int kq  = idx & 15;
            float4 v = *reinterpret_cast<const float4*>(W + j * 128 + c * 64 + 4 * kq);
            sW[(4 * kq + 0) * SW_STRIDE + j] = v.x;
            sW[(4 * kq + 1) * SW_STRIDE + j] = v.y;
            sW[(4 * kq + 2) * SW_STRIDE + j] = v.z;
            sW[(4 * kq + 3) * SW_STRIDE + j] = v.w;
        }
        __syncthreads();

        const float* xb = sX + (ty * 4) * SX_STRIDE;
        const float* wb = sW + tx * 8;

        #pragma unroll 8
        for (int k = 0; k < 64; k++) {
            float4 w0 = *reinterpret_cast<const float4*>(wb + k * SW_STRIDE);
            float4 w1 = *reinterpret_cast<const float4*>(wb + k * SW_STRIDE + 4);
            float x0 = xb[0 * SX_STRIDE + k];
            float x1 = xb[1 * SX_STRIDE + k];
            float x2 = xb[2 * SX_STRIDE + k];
            float x3 = xb[3 * SX_STRIDE + k];
            #pragma unroll
            for (int i = 0; i < 4; i++) {
                float xi = (i == 0) ? x0 : (i == 1) ? x1 : (i == 2) ? x2 : x3;
                acc[i][0] = fmaf(xi, w0.x, acc[i][0]);
                acc[i][1] = fmaf(xi, w0.y, acc[i][1]);
                acc[i][2] = fmaf(xi, w0.z, acc[i][2]);
                acc[i][3] = fmaf(xi, w0.w, acc[i][3]);
                acc[i][4] = fmaf(xi, w1.x, acc[i][4]);
                acc[i][5] = fmaf(xi, w1.y, acc[i][5]);
                acc[i][6] = fmaf(xi, w1.z, acc[i][6]);
                acc[i][7] = fmaf(xi, w1.w, acc[i][7]);
            }
        }
    }

    #pragma unroll
    for (int i = 0; i < 4; i++) {
        float ss = 0.f;
        #pragma unroll
        for (int j = 0; j < 8; j++) {
            float v = fmaxf(acc[i][j], 0.f);
            acc[i][j] = v;
            ss = fmaf(v, v, ss);
        }
        ss += __shfl_xor_sync(0xffffffffu, ss, 1);
        ss += __shfl_xor_sync(0xffffffffu, ss, 2);
        ss += __shfl_xor_sync(0xffffffffu, ss, 4);
        float s = 1.0f / fmaxf(sqrtf(ss), 1e-12f);

        int row = row0 + ty * 4 + i;
        if (row < nrows) {
            float* op = out + (size_t)row * DIM + tx * 8;
            *reinterpret_cast<float4*>(op) =
                make_float4(acc[i][0] * s, acc[i][1] * s, acc[i][2] * s, acc[i][3] * s);
            *reinterpret_cast<float4*>(op + 4) =
                make_float4(acc[i][4] * s, acc[i][5] * s, acc[i][6] * s, acc[i][7] * s);
        }
    }
}

// ---------------------------------------------------------------------------
static void build_csr(cudaStream_t s, const int* dst, const int* src, const float* w,
                      int* cnt, int* bsum, int* rowptr, int* pos, int2* edges, int nrows)
{
    cudaMemsetAsync(cnt, 0, nrows * sizeof(int), s);
    hist_kernel<<<(NEDGES + 255) / 256, 256, 0, s>>>(dst, cnt, NEDGES);
    int nb = (nrows + 1023) / 1024;
    scan_blocksum<<<nb, 1024, 0, s>>>(cnt, bsum, nrows);
    scan_bsums<<<1, 256, 0, s>>>(bsum, nb);
    scan_write<<<nb, 1024, 0, s>>>(cnt, bsum, rowptr, pos, nrows);
    scatter_edges<<<(NEDGES + 255) / 256, 256, 0, s>>>(dst, src, w, pos, edges, NEDGES);
}

extern "C" void kernel_launch(void* const* d_in, const int* in_sizes, int n_in,
                              void* d_out, int out_size)
{
    const float* user_emb = (const float*)d_in[0];
    const float* item_emb = (const float*)d_in[1];
    const float* Wu       = (const float*)d_in[2];   // [2][64][128]
    const float* Wi       = (const float*)d_in[3];
    const int*   u_idx    = (const int*)  d_in[4];
    const int*   i_idx    = (const int*)  d_in[5];
    const float* w_u2i    = (const float*)d_in[6];
    const float* w_i2u    = (const float*)d_in[7];

    float* out_u = (float*)d_out;
    float* out_i = out_u + (size_t)NUSERS * DIM;

    float *hu, *hi, *nu, *ni;
    int *cnt_u, *rp_u, *pos_u, *cnt_i, *rp_i, *pos_i, *bsum_u, *bsum_i;
    int2 *edge_u, *edge_i;
    cudaGetSymbolAddress((void**)&hu, g_hu);
    cudaGetSymbolAddress((void**)&hi, g_hi);
    cudaGetSymbolAddress((void**)&nu, g_nu);
    cudaGetSymbolAddress((void**)&ni, g_ni);
    cudaGetSymbolAddress((void**)&cnt_u, g_cnt_u);
    cudaGetSymbolAddress((void**)&rp_u,  g_rp_u);
    cudaGetSymbolAddress((void**)&pos_u, g_pos_u);
    cudaGetSymbolAddress((void**)&edge_u, g_edge_u);
    cudaGetSymbolAddress((void**)&cnt_i, g_cnt_i);
    cudaGetSymbolAddress((void**)&rp_i,  g_rp_i);
    cudaGetSymbolAddress((void**)&pos_i, g_pos_i);
    cudaGetSymbolAddress((void**)&edge_i, g_edge_i);
    cudaGetSymbolAddress((void**)&bsum_u, g_bsum_u);
    cudaGetSymbolAddress((void**)&bsum_i, g_bsum_i);

    static cudaStream_t s1 = nullptr;
    static cudaEvent_t evFork = nullptr, evHU = nullptr, evHI = nullptr, evEnd = nullptr;
    if (!s1) {
        cudaFuncSetAttribute(dense_norm_tiled,
                             cudaFuncAttributeMaxDynamicSharedMemorySize, DN_SMEM);
        cudaStreamCreateWithFlags(&s1, cudaStreamNonBlocking);
        cudaEventCreateWithFlags(&evFork, cudaEventDisableTiming);
        cudaEventCreateWithFlags(&evHU,   cudaEventDisableTiming);
        cudaEventCreateWithFlags(&evHI,   cudaEventDisableTiming);
        cudaEventCreateWithFlags(&evEnd,  cudaEventDisableTiming);
    }

    const int gather_u_blks = (NUSERS * 32 + 255) / 256;   // warp per row
    const int gather_i_blks = (NITEMS * 32 + 255) / 256;
    const int dense_u_blks  = (NUSERS + 127) / 128;
    const int dense_i_blks  = (NITEMS + 127) / 128;

    cudaStream_t s0 = 0;

    cudaEventRecord(evFork, s0);
    cudaStreamWaitEvent(s1, evFork, 0);

    // ---- CSR builds (independent; one per stream) ----
    build_csr(s0, u_idx, i_idx, w_u2i, cnt_u, bsum_u, rp_u, pos_u, edge_u, NUSERS);
    build_csr(s1, i_idx, u_idx, w_i2u, cnt_i, bsum_i, rp_i, pos_i, edge_i, NITEMS);

    // ---------------- Layer 0 ----------------
    spmm_gather<<<gather_u_blks, 256, 0, s0>>>(item_emb, rp_u, edge_u, nu, NUSERS);
    dense_norm_tiled<<<dense_u_blks, 256, DN_SMEM, s0>>>(user_emb, nu, Wu, hu, NUSERS);
    cudaEventRecord(evHU, s0);

    spmm_gather<<<gather_i_blks, 256, 0, s1>>>(user_emb, rp_i, edge_i, ni, NITEMS);
    dense_norm_tiled<<<dense_i_blks, 256, DN_SMEM, s1>>>(item_emb, ni, Wi, hi, NITEMS);
    cudaEventRecord(evHI, s1);

    // ---------------- Layer 1 ----------------
    cudaStreamWaitEvent(s0, evHI, 0);
    spmm_gather<<<gather_u_blks, 256, 0, s0>>>(hi, rp_u, edge_u, nu, NUSERS);
    dense_norm_tiled<<<dense_u_blks, 256, DN_SMEM, s0>>>(hu, nu, Wu + 64 * 128, out_u, NUSERS);

    cudaStreamWaitEvent(s1, evHU, 0);
    spmm_gather<<<gather_i_blks, 256, 0, s1>>>(hu, rp_i, edge_i, ni, NITEMS);
    dense_norm_tiled<<<dense_i_blks, 256, DN_SMEM, s1>>>(hi, ni, Wi + 64 * 128, out_i, NITEMS);

    cudaEventRecord(evEnd, s1);
    cudaStreamWaitEvent(s0, evEnd, 0);
}

// round 14
// speedup vs baseline: 1.2369x; 1.1173x over previous
#include <cuda_runtime.h>
#include <cuda_fp16.h>
#include <cstddef>

#define NUSERS 200000
#define NITEMS 100000
#define DIM    64
#define NEDGES 3200000

// -------- scratch (no allocations allowed; __device__ globals are the sanctioned path) ----
__device__ __align__(256) float g_hu[(size_t)NUSERS * DIM];
__device__ __align__(256) float g_hi[(size_t)NITEMS * DIM];
__device__ __align__(256) float g_nu[(size_t)NUSERS * DIM];
__device__ __align__(256) float g_ni[(size_t)NITEMS * DIM];

// fp16 shadow copies of gather sources (32 half2 per row)
__device__ __align__(256) __half2 g_ue_h[(size_t)NUSERS * 32];
__device__ __align__(256) __half2 g_ie_h[(size_t)NITEMS * 32];
__device__ __align__(256) __half2 g_hu_h[(size_t)NUSERS * 32];
__device__ __align__(256) __half2 g_hi_h[(size_t)NITEMS * 32];

// CSR scratch (rebuilt every call; no caching)
__device__ int  g_cnt_u[NUSERS];
__device__ int  g_rp_u[NUSERS + 1];
__device__ int  g_pos_u[NUSERS];
__device__ int2 g_edge_u[NEDGES];      // {src_item, w_bits}
__device__ int  g_cnt_i[NITEMS];
__device__ int  g_rp_i[NITEMS + 1];
__device__ int  g_pos_i[NITEMS];
__device__ int2 g_edge_i[NEDGES];      // {src_user, w_bits}
__device__ int  g_bsum_u[256];
__device__ int  g_bsum_i[256];

// ---------------------------------------------------------------------------
// fp32 -> fp16 conversion (float4 in, 2x half2 out as one 8B store)
// ---------------------------------------------------------------------------
__global__ void to_half_kernel(const float4* __restrict__ in,
                               __half2* __restrict__ out, int n4) {
    int i = blockIdx.x * blockDim.x + threadIdx.x;
    if (i >= n4) return;
    float4 v = in[i];
    __half2 a = __floats2half2_rn(v.x, v.y);
    __half2 b = __floats2half2_rn(v.z, v.w);
    float2 pk;
    pk.x = __uint_as_float(*reinterpret_cast<unsigned*>(&a));
    pk.y = __uint_as_float(*reinterpret_cast<unsigned*>(&b));
    *reinterpret_cast<float2*>(out + 2 * (size_t)i) = pk;
}

// ---------------------------------------------------------------------------
// CSR build: histogram -> 3-kernel exclusive scan -> edge scatter
// ---------------------------------------------------------------------------
__global__ void hist_kernel(const int* __restrict__ idx, int* __restrict__ cnt, int n) {
    int e = blockIdx.x * blockDim.x + threadIdx.x;
    if (e < n) atomicAdd(cnt + idx[e], 1);
}

__global__ void scan_blocksum(const int* __restrict__ cnt, int* __restrict__ bsum, int n) {
    __shared__ int sh[1024];
    int i = blockIdx.x * 1024 + threadIdx.x;
    int v = (i < n) ? cnt[i] : 0;
    sh[threadIdx.x] = v;
    __syncthreads();
    for (int o = 512; o > 0; o >>= 1) {
        if (threadIdx.x < o) sh[threadIdx.x] += sh[threadIdx.x + o];
        __syncthreads();
    }
    if (threadIdx.x == 0) bsum[blockIdx.x] = sh[0];
}

__global__ void scan_bsums(int* __restrict__ bsum, int nb) {   // single block, 256 thr
    __shared__ int sh[256];
    int t = threadIdx.x;
    int v = (t < nb) ? bsum[t] : 0;
    sh[t] = v;
    __syncthreads();
    for (int o = 1; o < 256; o <<= 1) {
        int x = (t >= o) ? sh[t - o] : 0;
        __syncthreads();
        sh[t] += x;
        __syncthreads();
    }
    if (t < nb) bsum[t] = sh[t] - v;   // exclusive
}

__global__ void scan_write(const int* __restrict__ cnt, const int* __restrict__ bsum,
                           int* __restrict__ rowptr, int* __restrict__ pos, int n) {
    __shared__ int sh[1024];
    int t = threadIdx.x;
    int i = blockIdx.x * 1024 + t;
    int v = (i < n) ? cnt[i] : 0;
    sh[t] = v;
    __syncthreads();
    for (int o = 1; o < 1024; o <<= 1) {
        int x = (t >= o) ? sh[t - o] : 0;
        __syncthreads();
        sh[t] += x;
        __syncthreads();
    }
    if (i < n) {
        int start = bsum[blockIdx.x] + sh[t] - v;
        rowptr[i] = start;
        pos[i]    = start;
    }
    if (i == 0) rowptr[n] = NEDGES;
}

__global__ void scatter_edges(const int* __restrict__ dst, const int* __restrict__ src,
                              const float* __restrict__ w, int* __restrict__ pos,
                              int2* __restrict__ edges, int n) {
    int e = blockIdx.x * blockDim.x + threadIdx.x;
    if (e >= n) return;
    int p = atomicAdd(pos + dst[e], 1);
    edges[p] = make_int2(src[e], __float_as_int(w[e]));
}

// ---------------------------------------------------------------------------
// Gather SpMM (fp16 source): out[r] = sum_j w_j * h[src_j]   (warp per row)
// EXACT 742us-best loop structure: 2-deep unroll, plain __ldg.
// Each lane reads one half2 (4B) -> warp reads 128B per gathered row.
// ---------------------------------------------------------------------------
__global__ void __launch_bounds__(256) spmm_gather_h(
    const __half2* __restrict__ h,      // [nsrc][32]
    const int*     __restrict__ rowptr,
    const int2*    __restrict__ edges,
    float*         __restrict__ out,
    int nrows)
{
    int warp = (blockIdx.x * 256 + threadIdx.x) >> 5;
    int lane = threadIdx.x & 31;
    if (warp >= nrows) return;

    int start = __ldg(rowptr + warp);
    int end   = __ldg(rowptr + warp + 1);

    float2 acc = make_float2(0.f, 0.f);
    int j = start;
    for (; j + 1 < end; j += 2) {
        int2 e0 = __ldg(edges + j);
        int2 e1 = __ldg(edges + j + 1);
        float2 f0 = __half22float2(__ldg(h + (size_t)e0.x * 32 + lane));
        float2 f1 = __half22float2(__ldg(h + (size_t)e1.x * 32 + lane));
        float w0 = __int_as_float(e0.y);
        float w1 = __int_as_float(e1.y);
        acc.x = fmaf(w0, f0.x, acc.x);
        acc.y = fmaf(w0, f0.y, acc.y);
        acc.x = fmaf(w1, f1.x, acc.x);
        acc.y = fmaf(w1, f1.y, acc.y);
    }
    if (j < end) {
        int2 e0 = __ldg(edges + j);
        float2 f0 = __half22float2(__ldg(h + (size_t)e0.x * 32 + lane));
        float w0 = __int_as_float(e0.y);
        acc.x = fmaf(w0, f0.x, acc.x);
        acc.y = fmaf(w0, f0.y, acc.y);
    }
    *reinterpret_cast<float2*>(out + (size_t)warp * DIM + 2 * lane) = acc;
}

// ---------------------------------------------------------------------------
// Register-tiled fused dense+relu+L2norm, K split in 2 chunks of 64.
// EXACT 742us-best mainloop (k-by-1, scalar x LDS, no spills).
// Optional fp16 shadow output emitted in the epilogue only.
// ---------------------------------------------------------------------------
#define SX_STRIDE 68
#define SW_STRIDE 68
#define DN_SMEM ((128 * SX_STRIDE + 64 * SW_STRIDE) * 4)

__global__ void __launch_bounds__(256, 4) dense_norm_tiled(
    const float* __restrict__ h,
    const float* __restrict__ neigh,
    const float* __restrict__ W,       // [64][128] row-major
    float*       __restrict__ out,
    __half*      __restrict__ out16,   // nullable fp16 shadow
    int nrows)
{
    extern __shared__ float smem[];
    float* sX = smem;                    // [128][SX_STRIDE]
    float* sW = smem + 128 * SX_STRIDE;  // [64][SW_STRIDE]

    const int t    = threadIdx.x;
    const int tx   = t & 7;
    const int ty   = t >> 3;
    const int row0 = blockIdx.x * 128;

    float acc[4][8];
    #pragma unroll
    for (int i = 0; i < 4; i++)
        #pragma unroll
        for (int j = 0; j < 8; j++) acc[i][j] = 0.f;

    #pragma unroll
    for (int c = 0; c < 2; c++) {
        const float* xsrc = (c == 0) ? h : neigh;
        if (c) __syncthreads();

        #pragma unroll
        for (int i = 0; i < 8; i++) {
            int idx = t + i * 256;
            int m   = idx >> 4;
            int kq  = idx & 15;
            int row = row0 + m;
            float4 v = make_float4(0.f, 0.f, 0.f, 0.f);
            if (row < nrows)
                v = *reinterpret_cast<const float4*>(xsrc + (size_t)row * DIM + 4 * kq);
            *reinterpret_cast<float4*>(sX + m * SX_STRIDE + 4 * kq) = v;
        }
        #pragma unroll
        for (int i = 0; i < 4; i++) {
            int idx = t + i * 256;
            int j   = idx >> 4;
            int kq  = idx & 15;
            float4 v = *reinterpret_cast<const float4*>(W + j * 128 + c * 64 + 4 * kq);
            sW[(4 * kq + 0) * SW_STRIDE + j] = v.x;
            sW[(4 * kq + 1) * SW_STRIDE + j] = v.y;
            sW[(4 * kq + 2) * SW_STRIDE + j] = v.z;
            sW[(4 * kq + 3) * SW_STRIDE + j] = v.w;
        }
        __syncthreads();

        const float* xb = sX + (ty * 4) * SX_STRIDE;
        const float* wb = sW + tx * 8;

        #pragma unroll 8
        for (int k = 0; k < 64; k++) {
            float4 w0 = *reinterpret_cast<const float4*>(wb + k * SW_STRIDE);
            float4 w1 = *reinterpret_cast<const float4*>(wb + k * SW_STRIDE + 4);
            float x0 = xb[0 * SX_STRIDE + k];
            float x1 = xb[1 * SX_STRIDE + k];
            float x2 = xb[2 * SX_STRIDE + k];
            float x3 = xb[3 * SX_STRIDE + k];
            #pragma unroll
            for (int i = 0; i < 4; i++) {
                float xi = (i == 0) ? x0 : (i == 1) ? x1 : (i == 2) ? x2 : x3;
                acc[i][0] = fmaf(xi, w0.x, acc[i][0]);
                acc[i][1] = fmaf(xi, w0.y, acc[i][1]);
                acc[i][2] = fmaf(xi, w0.z, acc[i][2]);
                acc[i][3] = fmaf(xi, w0.w, acc[i][3]);
                acc[i][4] = fmaf(xi, w1.x, acc[i][4]);
                acc[i][5] = fmaf(xi, w1.y, acc[i][5]);
                acc[i][6] = fmaf(xi, w1.z, acc[i][6]);
                acc[i][7] = fmaf(xi, w1.w, acc[i][7]);
            }
        }
    }

    #pragma unroll
    for (int i = 0; i < 4; i++) {
        float ss = 0.f;
        #pragma unroll
        for (int j = 0; j < 8; j++) {
            float v = fmaxf(acc[i][j], 0.f);
            acc[i][j] = v;
            ss = fmaf(v, v, ss);
        }
        ss += __shfl_xor_sync(0xffffffffu, ss, 1);
        ss += __shfl_xor_sync(0xffffffffu, ss, 2);
        ss += __shfl_xor_sync(0xffffffffu, ss, 4);
        float s = 1.0f / fmaxf(sqrtf(ss), 1e-12f);

        int row = row0 + ty * 4 + i;
        if (row < nrows) {
            float o0 = acc[i][0] * s, o1 = acc[i][1] * s, o2 = acc[i][2] * s, o3 = acc[i][3] * s;
            float o4 = acc[i][4] * s, o5 = acc[i][5] * s, o6 = acc[i][6] * s, o7 = acc[i][7] * s;
            float* op = out + (size_t)row * DIM + tx * 8;
            *reinterpret_cast<float4*>(op)     = make_float4(o0, o1, o2, o3);
            *reinterpret_cast<float4*>(op + 4) = make_float4(o4, o5, o6, o7);

            if (out16) {
                __half2 p0 = __floats2half2_rn(o0, o1);
                __half2 p1 = __floats2half2_rn(o2, o3);
                __half2 p2 = __floats2half2_rn(o4, o5);
                __half2 p3 = __floats2half2_rn(o6, o7);
                uint4 pk;
                pk.x = *reinterpret_cast<unsigned*>(&p0);
                pk.y = *reinterpret_cast<unsigned*>(&p1);
                pk.z = *reinterpret_cast<unsigned*>(&p2);
                pk.w = *reinterpret_cast<unsigned*>(&p3);
                *reinterpret_cast<uint4*>(out16 + (size_t)row * DIM + tx * 8) = pk;
            }
        }
    }
}

// ---------------------------------------------------------------------------
static void build_csr(cudaStream_t s, const int* dst, const int* src, const float* w,
                      int* cnt, int* bsum, int* rowptr, int* pos, int2* edges, int nrows)
{
    cudaMemsetAsync(cnt, 0, nrows * sizeof(int), s);
    hist_kernel<<<(NEDGES + 255) / 256, 256, 0, s>>>(dst, cnt, NEDGES);
    int nb = (nrows + 1023) / 1024;
    scan_blocksum<<<nb, 1024, 0, s>>>(cnt, bsum, nrows);
    scan_bsums<<<1, 256, 0, s>>>(bsum, nb);
    scan_write<<<nb, 1024, 0, s>>>(cnt, bsum, rowptr, pos, nrows);
    scatter_edges<<<(NEDGES + 255) / 256, 256, 0, s>>>(dst, src, w, pos, edges, NEDGES);
}

extern "C" void kernel_launch(void* const* d_in, const int* in_sizes, int n_in,
                              void* d_out, int out_size)
{
    const float* user_emb = (const float*)d_in[0];
    const float* item_emb = (const float*)d_in[1];
    const float* Wu       = (const float*)d_in[2];   // [2][64][128]
    const float* Wi       = (const float*)d_in[3];
    const int*   u_idx    = (const int*)  d_in[4];
    const int*   i_idx    = (const int*)  d_in[5];
    const float* w_u2i    = (const float*)d_in[6];
    const float* w_i2u    = (const float*)d_in[7];

    float* out_u = (float*)d_out;
    float* out_i = out_u + (size_t)NUSERS * DIM;

    float *hu, *hi, *nu, *ni;
    __half2 *ue_h, *ie_h, *hu_h, *hi_h;
    int *cnt_u, *rp_u, *pos_u, *cnt_i, *rp_i, *pos_i, *bsum_u, *bsum_i;
    int2 *edge_u, *edge_i;
    cudaGetSymbolAddress((void**)&hu, g_hu);
    cudaGetSymbolAddress((void**)&hi, g_hi);
    cudaGetSymbolAddress((void**)&nu, g_nu);
    cudaGetSymbolAddress((void**)&ni, g_ni);
    cudaGetSymbolAddress((void**)&ue_h, g_ue_h);
    cudaGetSymbolAddress((void**)&ie_h, g_ie_h);
    cudaGetSymbolAddress((void**)&hu_h, g_hu_h);
    cudaGetSymbolAddress((void**)&hi_h, g_hi_h);
    cudaGetSymbolAddress((void**)&cnt_u, g_cnt_u);
    cudaGetSymbolAddress((void**)&rp_u,  g_rp_u);
    cudaGetSymbolAddress((void**)&pos_u, g_pos_u);
    cudaGetSymbolAddress((void**)&edge_u, g_edge_u);
    cudaGetSymbolAddress((void**)&cnt_i, g_cnt_i);
    cudaGetSymbolAddress((void**)&rp_i,  g_rp_i);
    cudaGetSymbolAddress((void**)&pos_i, g_pos_i);
    cudaGetSymbolAddress((void**)&edge_i, g_edge_i);
    cudaGetSymbolAddress((void**)&bsum_u, g_bsum_u);
    cudaGetSymbolAddress((void**)&bsum_i, g_bsum_i);

    static cudaStream_t s1 = nullptr;
    static cudaEvent_t evFork = nullptr, evHU = nullptr, evHI = nullptr, evEnd = nullptr;
    if (!s1) {
        cudaFuncSetAttribute(dense_norm_tiled,
                             cudaFuncAttributeMaxDynamicSharedMemorySize, DN_SMEM);
        cudaStreamCreateWithFlags(&s1, cudaStreamNonBlocking);
        cudaEventCreateWithFlags(&evFork, cudaEventDisableTiming);
        cudaEventCreateWithFlags(&evHU,   cudaEventDisableTiming);
        cudaEventCreateWithFlags(&evHI,   cudaEventDisableTiming);
        cudaEventCreateWithFlags(&evEnd,  cudaEventDisableTiming);
    }

    const int gather_u_blks = (NUSERS * 32 + 255) / 256;   // warp per row
    const int gather_i_blks = (NITEMS * 32 + 255) / 256;
    const int dense_u_blks  = (NUSERS + 127) / 128;
    const int dense_i_blks  = (NITEMS + 127) / 128;
    const int cu4 = NUSERS * DIM / 4;
    const int ci4 = NITEMS * DIM / 4;

    cudaStream_t s0 = 0;

    cudaEventRecord(evFork, s0);
    cudaStreamWaitEvent(s1, evFork, 0);

    // ---- fp16 shadows of layer-0 gather sources + CSR builds (overlapped) ----
    to_half_kernel<<<(ci4 + 255) / 256, 256, 0, s0>>>((const float4*)item_emb, ie_h, ci4);
    build_csr(s0, u_idx, i_idx, w_u2i, cnt_u, bsum_u, rp_u, pos_u, edge_u, NUSERS);

    to_half_kernel<<<(cu4 + 255) / 256, 256, 0, s1>>>((const float4*)user_emb, ue_h, cu4);
    build_csr(s1, i_idx, u_idx, w_i2u, cnt_i, bsum_i, rp_i, pos_i, edge_i, NITEMS);

    // ---------------- Layer 0 ----------------
    spmm_gather_h<<<gather_u_blks, 256, 0, s0>>>(ie_h, rp_u, edge_u, nu, NUSERS);
    dense_norm_tiled<<<dense_u_blks, 256, DN_SMEM, s0>>>(
        user_emb, nu, Wu, hu, (__half*)hu_h, NUSERS);
    cudaEventRecord(evHU, s0);

    spmm_gather_h<<<gather_i_blks, 256, 0, s1>>>(ue_h, rp_i, edge_i, ni, NITEMS);
    dense_norm_tiled<<<dense_i_blks, 256, DN_SMEM, s1>>>(
        item_emb, ni, Wi, hi, (__half*)hi_h, NITEMS);
    cudaEventRecord(evHI, s1);

    // ---------------- Layer 1 ----------------
    cudaStreamWaitEvent(s0, evHI, 0);
    spmm_gather_h<<<gather_u_blks, 256, 0, s0>>>(hi_h, rp_u, edge_u, nu, NUSERS);
    dense_norm_tiled<<<dense_u_blks, 256, DN_SMEM, s0>>>(
        hu, nu, Wu + 64 * 128, out_u, (__half*)nullptr, NUSERS);

    cudaStreamWaitEvent(s1, evHU, 0);
    spmm_gather_h<<<gather_i_blks, 256, 0, s1>>>(hu_h, rp_i, edge_i, ni, NITEMS);
    dense_norm_tiled<<<dense_i_blks, 256, DN_SMEM, s1>>>(
        hi, ni, Wi + 64 * 128, out_i, (__half*)nullptr, NITEMS);

    cudaEventRecord(evEnd, s1);
    cudaStreamWaitEvent(s0, evEnd, 0);
}

// round 16
// speedup vs baseline: 1.2372x; 1.0003x over previous
#include <cuda_runtime.h>
#include <cstddef>

#define NUSERS 200000
#define NITEMS 100000
#define DIM    64
#define NEDGES 3200000

// -------- scratch (no allocations allowed; __device__ globals are the sanctioned path) ----
__device__ __align__(256) float g_hu[(size_t)NUSERS * DIM];
__device__ __align__(256) float g_hi[(size_t)NITEMS * DIM];
__device__ __align__(256) float g_nu[(size_t)NUSERS * DIM];
__device__ __align__(256) float g_ni[(size_t)NITEMS * DIM];

// CSR scratch (rebuilt every call; no caching)
__device__ int  g_cnt_u[NUSERS];
__device__ int  g_rp_u[NUSERS + 1];
__device__ int  g_pos_u[NUSERS];
__device__ __align__(16) int2 g_edge_u[NEDGES];   // {src_item, w_bits}
__device__ int  g_cnt_i[NITEMS];
__device__ int  g_rp_i[NITEMS + 1];
__device__ int  g_pos_i[NITEMS];
__device__ __align__(16) int2 g_edge_i[NEDGES];   // {src_user, w_bits}
__device__ int  g_bsum_u[256];
__device__ int  g_bsum_i[256];

// ---------------------------------------------------------------------------
// CSR build: histogram -> 3-kernel exclusive scan -> edge scatter
// ---------------------------------------------------------------------------
__global__ void hist_kernel(const int* __restrict__ idx, int* __restrict__ cnt, int n) {
    int e = blockIdx.x * blockDim.x + threadIdx.x;
    if (e < n) atomicAdd(cnt + idx[e], 1);
}

__global__ void scan_blocksum(const int* __restrict__ cnt, int* __restrict__ bsum, int n) {
    __shared__ int sh[1024];
    int i = blockIdx.x * 1024 + threadIdx.x;
    int v = (i < n) ? cnt[i] : 0;
    sh[threadIdx.x] = v;
    __syncthreads();
    for (int o = 512; o > 0; o >>= 1) {
        if (threadIdx.x < o) sh[threadIdx.x] += sh[threadIdx.x + o];
        __syncthreads();
    }
    if (threadIdx.x == 0) bsum[blockIdx.x] = sh[0];
}

__global__ void scan_bsums(int* __restrict__ bsum, int nb) {   // single block, 256 thr
    __shared__ int sh[256];
    int t = threadIdx.x;
    int v = (t < nb) ? bsum[t] : 0;
    sh[t] = v;
    __syncthreads();
    for (int o = 1; o < 256; o <<= 1) {
        int x = (t >= o) ? sh[t - o] : 0;
        __syncthreads();
        sh[t] += x;
        __syncthreads();
    }
    if (t < nb) bsum[t] = sh[t] - v;   // exclusive
}

__global__ void scan_write(const int* __restrict__ cnt, const int* __restrict__ bsum,
                           int* __restrict__ rowptr, int* __restrict__ pos, int n) {
    __shared__ int sh[1024];
    int t = threadIdx.x;
    int i = blockIdx.x * 1024 + t;
    int v = (i < n) ? cnt[i] : 0;
    sh[t] = v;
    __syncthreads();
    for (int o = 1; o < 1024; o <<= 1) {
        int x = (t >= o) ? sh[t - o] : 0;
        __syncthreads();
        sh[t] += x;
        __syncthreads();
    }
    if (i < n) {
        int start = bsum[blockIdx.x] + sh[t] - v;
        rowptr[i] = start;
        pos[i]    = start;
    }
    if (i == 0) rowptr[n] = NEDGES;
}

__global__ void scatter_edges(const int* __restrict__ dst, const int* __restrict__ src,
                              const float* __restrict__ w, int* __restrict__ pos,
                              int2* __restrict__ edges, int n) {
    int e = blockIdx.x * blockDim.x + threadIdx.x;
    if (e >= n) return;
    int p = atomicAdd(pos + dst[e], 1);
    edges[p] = make_int2(src[e], __float_as_int(w[e]));
}

// ---------------------------------------------------------------------------
// Gather SpMM: out[r] = sum_{j in row r} w_j * h[src_j]   (warp per row)
// 2-deep edge unroll with PAIRED int4 meta load (one 16B uniform LDG covers
// both edges) -> 1.5 LDG instructions per edge instead of 2.
// ---------------------------------------------------------------------------
__global__ void __launch_bounds__(256) spmm_gather(
    const float* __restrict__ h,
    const int*   __restrict__ rowptr,
    const int2*  __restrict__ edges,
    float*       __restrict__ out,
    int nrows)
{
    int warp = (blockIdx.x * 256 + threadIdx.x) >> 5;
    int lane = threadIdx.x & 31;
    if (warp >= nrows) return;

    int start = __ldg(rowptr + warp);
    int end   = __ldg(rowptr + warp + 1);

    float2 acc = make_float2(0.f, 0.f);
    int j = start;

    // peel one edge if start is odd (align the int4 pair loads to 16B)
    if ((j & 1) && j < end) {
        int2 e0 = __ldg(edges + j);
        float2 v0 = *reinterpret_cast<const float2*>(h + (size_t)e0.x * DIM + 2 * lane);
        float w0 = __int_as_float(e0.y);
        acc.x = fmaf(w0, v0.x, acc.x);
        acc.y = fmaf(w0, v0.y, acc.y);
        j++;
    }

    for (; j + 1 < end; j += 2) {
        int4 m = __ldg(reinterpret_cast<const int4*>(edges + j));   // 16B aligned
        float2 v0 = *reinterpret_cast<const float2*>(h + (size_t)m.x * DIM + 2 * lane);
        float2 v1 = *reinterpret_cast<const float2*>(h + (size_t)m.z * DIM + 2 * lane);
        float w0 = __int_as_float(m.y);
        float w1 = __int_as_float(m.w);
        acc.x = fmaf(w0, v0.x, acc.x);
        acc.y = fmaf(w0, v0.y, acc.y);
        acc.x = fmaf(w1, v1.x, acc.x);
        acc.y = fmaf(w1, v1.y, acc.y);
    }
    if (j < end) {
        int2 e0 = __ldg(edges + j);
        float2 v0 = *reinterpret_cast<const float2*>(h + (size_t)e0.x * DIM + 2 * lane);
        float w0 = __int_as_float(e0.y);
        acc.x = fmaf(w0, v0.x, acc.x);
        acc.y = fmaf(w0, v0.y, acc.y);
    }
    *reinterpret_cast<float2*>(out + (size_t)warp * DIM + 2 * lane) = acc;
}

// ---------------------------------------------------------------------------
// Register-tiled fused dense+relu+L2norm, K split in 2 chunks of 64.
// EXACT 742us-best mainloop (k-by-1, scalar x LDS, no spills, 4 blocks/SM).
// ---------------------------------------------------------------------------
#define SX_STRIDE 68
#define SW_STRIDE 68
#define DN_SMEM ((128 * SX_STRIDE + 64 * SW_STRIDE) * 4)

__global__ void __launch_bounds__(256, 4) dense_norm_tiled(
    const float* __restrict__ h,
    const float* __restrict__ neigh,
    const float* __restrict__ W,     // [64][128] row-major
    float*       __restrict__ out,
    int nrows)
{
    extern __shared__ float smem[];
    float* sX = smem;                    // [128][SX_STRIDE]
    float* sW = smem + 128 * SX_STRIDE;  // [64][SW_STRIDE]

    const int t    = threadIdx.x;
    const int tx   = t & 7;
    const int ty   = t >> 3;
    const int row0 = blockIdx.x * 128;

    float acc[4][8];
    #pragma unroll
    for (int i = 0; i < 4; i++)
        #pragma unroll
        for (int j = 0; j < 8; j++) acc[i][j] = 0.f;

    #pragma unroll
    for (int c = 0; c < 2; c++) {
        const float* xsrc = (c == 0) ? h : neigh;
        if (c) __syncthreads();

        #pragma unroll
        for (int i = 0; i < 8; i++) {
            int idx = t + i * 256;
            int m   = idx >> 4;
            int kq  = idx & 15;
            int row = row0 + m;
            float4 v = make_float4(0.f, 0.f, 0.f, 0.f);
            if (row < nrows)
                v = *reinterpret_cast<const float4*>(xsrc + (size_t)row * DIM + 4 * kq);
            *reinterpret_cast<float4*>(sX + m * SX_STRIDE + 4 * kq) = v;
        }
        #pragma unroll
        for (int i = 0; i < 4; i++) {
            int idx = t + i * 256;
            int j   = idx >> 4;
            int kq  = idx & 15;
            float4 v = *reinterpret_cast<const float4*>(W + j * 128 + c * 64 + 4 * kq);
            sW[(4 * kq + 0) * SW_STRIDE + j] = v.x;
            sW[(4 * kq + 1) * SW_STRIDE + j] = v.y;
            sW[(4 * kq + 2) * SW_STRIDE + j] = v.z;
            sW[(4 * kq + 3) * SW_STRIDE + j] = v.w;
        }
        __syncthreads();

        const float* xb = sX + (ty * 4) * SX_STRIDE;
        const float* wb = sW + tx * 8;

        #pragma unroll 8
        for (int k = 0; k < 64; k++) {
            float4 w0 = *reinterpret_cast<const float4*>(wb + k * SW_STRIDE);
            float4 w1 = *reinterpret_cast<const float4*>(wb + k * SW_STRIDE + 4);
            float x0 = xb[0 * SX_STRIDE + k];
            float x1 = xb[1 * SX_STRIDE + k];
            float x2 = xb[2 * SX_STRIDE + k];
            float x3 = xb[3 * SX_STRIDE + k];
            #pragma unroll
            for (int i = 0; i < 4; i++) {
                float xi = (i == 0) ? x0 : (i == 1) ? x1 : (i == 2) ? x2 : x3;
                acc[i][0] = fmaf(xi, w0.x, acc[i][0]);
                acc[i][1] = fmaf(xi, w0.y, acc[i][1]);
                acc[i][2] = fmaf(xi, w0.z, acc[i][2]);
                acc[i][3] = fmaf(xi, w0.w, acc[i][3]);
                acc[i][4] = fmaf(xi, w1.x, acc[i][4]);
                acc[i][5] = fmaf(xi, w1.y, acc[i][5]);
                acc[i][6] = fmaf(xi, w1.z, acc[i][6]);
                acc[i][7] = fmaf(xi, w1.w, acc[i][7]);
            }
        }
    }

    #pragma unroll
    for (int i = 0; i < 4; i++) {
        float ss = 0.f;
        #pragma unroll
        for (int j = 0; j < 8; j++) {
            float v = fmaxf(acc[i][j], 0.f);
            acc[i][j] = v;
            ss = fmaf(v, v, ss);
        }
        ss += __shfl_xor_sync(0xffffffffu, ss, 1);
        ss += __shfl_xor_sync(0xffffffffu, ss, 2);
        ss += __shfl_xor_sync(0xffffffffu, ss, 4);
        float s = 1.0f / fmaxf(sqrtf(ss), 1e-12f);

        int row = row0 + ty * 4 + i;
        if (row < nrows) {
            float* op = out + (size_t)row * DIM + tx * 8;
            *reinterpret_cast<float4*>(op) =
                make_float4(acc[i][0] * s, acc[i][1] * s, acc[i][2] * s, acc[i][3] * s);
            *reinterpret_cast<float4*>(op + 4) =
                make_float4(acc[i][4] * s, acc[i][5] * s, acc[i][6] * s, acc[i][7] * s);
        }
    }
}

// ---------------------------------------------------------------------------
static void build_csr(cudaStream_t s, const int* dst, const int* src, const float* w,
                      int* cnt, int* bsum, int* rowptr, int* pos, int2* edges, int nrows)
{
    cudaMemsetAsync(cnt, 0, nrows * sizeof(int), s);
    hist_kernel<<<(NEDGES + 255) / 256, 256, 0, s>>>(dst, cnt, NEDGES);
    int nb = (nrows + 1023) / 1024;
    scan_blocksum<<<nb, 1024, 0, s>>>(cnt, bsum, nrows);
    scan_bsums<<<1, 256, 0, s>>>(bsum, nb);
    scan_write<<<nb, 1024, 0, s>>>(cnt, bsum, rowptr, pos, nrows);
    scatter_edges<<<(NEDGES + 255) / 256, 256, 0, s>>>(dst, src, w, pos, edges, NEDGES);
}

extern "C" void kernel_launch(void* const* d_in, const int* in_sizes, int n_in,
                              void* d_out, int out_size)
{
    const float* user_emb = (const float*)d_in[0];
    const float* item_emb = (const float*)d_in[1];
    const float* Wu       = (const float*)d_in[2];   // [2][64][128]
    const float* Wi       = (const float*)d_in[3];
    const int*   u_idx    = (const int*)  d_in[4];
    const int*   i_idx    = (const int*)  d_in[5];
    const float* w_u2i    = (const float*)d_in[6];
    const float* w_i2u    = (const float*)d_in[7];

    float* out_u = (float*)d_out;
    float* out_i = out_u + (size_t)NUSERS * DIM;

    float *hu, *hi, *nu, *ni;
    int *cnt_u, *rp_u, *pos_u, *cnt_i, *rp_i, *pos_i, *bsum_u, *bsum_i;
    int2 *edge_u, *edge_i;
    cudaGetSymbolAddress((void**)&hu, g_hu);
    cudaGetSymbolAddress((void**)&hi, g_hi);
    cudaGetSymbolAddress((void**)&nu, g_nu);
    cudaGetSymbolAddress((void**)&ni, g_ni);
    cudaGetSymbolAddress((void**)&cnt_u, g_cnt_u);
    cudaGetSymbolAddress((void**)&rp_u,  g_rp_u);
    cudaGetSymbolAddress((void**)&pos_u, g_pos_u);
    cudaGetSymbolAddress((void**)&edge_u, g_edge_u);
    cudaGetSymbolAddress((void**)&cnt_i, g_cnt_i);
    cudaGetSymbolAddress((void**)&rp_i,  g_rp_i);
    cudaGetSymbolAddress((void**)&pos_i, g_pos_i);
    cudaGetSymbolAddress((void**)&edge_i, g_edge_i);
    cudaGetSymbolAddress((void**)&bsum_u, g_bsum_u);
    cudaGetSymbolAddress((void**)&bsum_i, g_bsum_i);

    static cudaStream_t s1 = nullptr;
    static cudaEvent_t evFork = nullptr, evHU = nullptr, evHI = nullptr, evEnd = nullptr;
    if (!s1) {
        cudaFuncSetAttribute(dense_norm_tiled,
                             cudaFuncAttributeMaxDynamicSharedMemorySize, DN_SMEM);
        cudaStreamCreateWithFlags(&s1, cudaStreamNonBlocking);
        cudaEventCreateWithFlags(&evFork, cudaEventDisableTiming);
        cudaEventCreateWithFlags(&evHU,   cudaEventDisableTiming);
        cudaEventCreateWithFlags(&evHI,   cudaEventDisableTiming);
        cudaEventCreateWithFlags(&evEnd,  cudaEventDisableTiming);
    }

    const int gather_u_blks = (NUSERS * 32 + 255) / 256;   // warp per row
    const int gather_i_blks = (NITEMS * 32 + 255) / 256;
    const int dense_u_blks  = (NUSERS + 127) / 128;
    const int dense_i_blks  = (NITEMS + 127) / 128;

    cudaStream_t s0 = 0;

    cudaEventRecord(evFork, s0);
    cudaStreamWaitEvent(s1, evFork, 0);

    // ---- CSR builds (independent; one per stream) ----
    build_csr(s0, u_idx, i_idx, w_u2i, cnt_u, bsum_u, rp_u, pos_u, edge_u, NUSERS);
    build_csr(s1, i_idx, u_idx, w_i2u, cnt_i, bsum_i, rp_i, pos_i, edge_i, NITEMS);

    // ---------------- Layer 0 ----------------
    spmm_gather<<<gather_u_blks, 256, 0, s0>>>(item_emb, rp_u, edge_u, nu, NUSERS);
    dense_norm_tiled<<<dense_u_blks, 256, DN_SMEM, s0>>>(user_emb, nu, Wu, hu, NUSERS);
    cudaEventRecord(evHU, s0);

    spmm_gather<<<gather_i_blks, 256, 0, s1>>>(user_emb, rp_i, edge_i, ni, NITEMS);
    dense_norm_tiled<<<dense_i_blks, 256, DN_SMEM, s1>>>(item_emb, ni, Wi, hi, NITEMS);
    cudaEventRecord(evHI, s1);

    // ---------------- Layer 1 ----------------
    cudaStreamWaitEvent(s0, evHI, 0);
    spmm_gather<<<gather_u_blks, 256, 0, s0>>>(hi, rp_u, edge_u, nu, NUSERS);
    dense_norm_tiled<<<dense_u_blks, 256, DN_SMEM, s0>>>(hu, nu, Wu + 64 * 128, out_u, NUSERS);

    cudaStreamWaitEvent(s1, evHU, 0);
    spmm_gather<<<gather_i_blks, 256, 0, s1>>>(hu, rp_i, edge_i, ni, NITEMS);
    dense_norm_tiled<<<dense_i_blks, 256, DN_SMEM, s1>>>(hi, ni, Wi + 64 * 128, out_i, NITEMS);

    cudaEventRecord(evEnd, s1);
    cudaStreamWaitEvent(s0, evEnd, 0);
}